// round 3
// baseline (speedup 1.0000x reference)
#include <cuda_runtime.h>

// Model dims (fixed by the problem)
#define Bsz  64
#define Tt   128
#define Cc   384
#define Hh   6
#define DHh  64
#define Ll   6
#define FFf  1536
#define Vv   25000
#define NTOK (Bsz * Tt)
#define LN_EPS 1e-5f

// ---------------- scratch (device globals: allocation-free) ----------------
__device__ float g_x[NTOK * Cc];
__device__ float g_h[NTOK * Cc];
__device__ float g_q[NTOK * Cc];
__device__ float g_k[NTOK * Cc];
__device__ float g_v[NTOK * Cc];
__device__ float g_att[NTOK * Cc];
__device__ float g_ff[NTOK * FFf];
__device__ float g_nll[NTOK];

// ---------------- block reductions (deterministic) ----------------
template <int NW>
__device__ __forceinline__ float blk_sum(float v) {
    __shared__ float sh[NW];
    int lane = threadIdx.x & 31, w = threadIdx.x >> 5;
#pragma unroll
    for (int o = 16; o > 0; o >>= 1) v += __shfl_down_sync(0xffffffffu, v, o);
    if (lane == 0) sh[w] = v;
    __syncthreads();
    if (threadIdx.x == 0) {
        float t = 0.f;
#pragma unroll
        for (int i = 0; i < NW; i++) t += sh[i];
        sh[0] = t;
    }
    __syncthreads();
    float r = sh[0];
    __syncthreads();
    return r;
}

template <int NW>
__device__ __forceinline__ float blk_max(float v) {
    __shared__ float sh[NW];
    int lane = threadIdx.x & 31, w = threadIdx.x >> 5;
#pragma unroll
    for (int o = 16; o > 0; o >>= 1) v = fmaxf(v, __shfl_down_sync(0xffffffffu, v, o));
    if (lane == 0) sh[w] = v;
    __syncthreads();
    if (threadIdx.x == 0) {
        float t = sh[0];
#pragma unroll
        for (int i = 1; i < NW; i++) t = fmaxf(t, sh[i]);
        sh[0] = t;
    }
    __syncthreads();
    float r = sh[0];
    __syncthreads();
    return r;
}

// ---------------- embedding ----------------
__global__ void embed_kernel(const int* __restrict__ idx,
                             const float* __restrict__ tok,
                             const float* __restrict__ pos) {
    int i = blockIdx.x, c = threadIdx.x;
    int t = i % Tt;
    g_x[(size_t)i * Cc + c] = tok[(size_t)idx[i] * Cc + c] + pos[(size_t)t * Cc + c];
}

// ---------------- layernorm (128 threads, 3 elems/thread) ----------------
__global__ void ln_kernel(const float* __restrict__ in, const float* __restrict__ g,
                          const float* __restrict__ b, float* __restrict__ out) {
    int row = blockIdx.x;
    const float* p = in + (size_t)row * Cc;
    int c = threadIdx.x;
    float x0 = p[c], x1 = p[c + 128], x2 = p[c + 256];
    float s = blk_sum<4>(x0 + x1 + x2);
    float mu = s * (1.f / Cc);
    float d0 = x0 - mu, d1 = x1 - mu, d2 = x2 - mu;
    float s2 = blk_sum<4>(d0 * d0 + d1 * d1 + d2 * d2);
    float w = rsqrtf(s2 * (1.f / Cc) + LN_EPS);
    float* q = out + (size_t)row * Cc;
    q[c]       = d0 * w * g[c]       + b[c];
    q[c + 128] = d1 * w * g[c + 128] + b[c + 128];
    q[c + 256] = d2 * w * g[c + 256] + b[c + 256];
}

// ---------------- SGEMM: C[M,N] = A[M,K] @ B[K,N] (+bias, relu, +res) ----
// 128x128 tile, BK=16, 256 threads, 8x8 per-thread register tile.
#define BM 128
#define BN 128
#define BK 16
#define TM 8
#define TN 8

template <bool BIAS, bool RELU, bool RES>
__device__ __forceinline__ void sgemm_body(const float* __restrict__ A,
                                           const float* __restrict__ Bm,
                                           const float* __restrict__ bias,
                                           const float* __restrict__ res,
                                           float* __restrict__ Cm,
                                           int M, int N, int K) {
    __shared__ float As[BK][BM];
    __shared__ float Bs[BK][BN];
    int tid = threadIdx.x;
    int tx = tid & 15, ty = tid >> 4;
    int m0 = blockIdx.y * BM, n0 = blockIdx.x * BN;

    float acc[TM][TN];
#pragma unroll
    for (int i = 0; i < TM; i++)
#pragma unroll
        for (int j = 0; j < TN; j++) acc[i][j] = 0.f;

    for (int k0 = 0; k0 < K; k0 += BK) {
        // A tile: 128x16 = 512 float4
#pragma unroll
        for (int r = 0; r < 2; r++) {
            int f = tid + r * 256;
            int m = f >> 2;
            int kk = (f & 3) * 4;
            float4 a = *(const float4*)(A + (size_t)(m0 + m) * K + k0 + kk);
            As[kk + 0][m] = a.x; As[kk + 1][m] = a.y;
            As[kk + 2][m] = a.z; As[kk + 3][m] = a.w;
        }
        // B tile: 16x128 = 512 float4 (N guaranteed %4==0)
#pragma unroll
        for (int r = 0; r < 2; r++) {
            int f = tid + r * 256;
            int kk = f >> 5;
            int n = (f & 31) * 4;
            float4 bv;
            if (n0 + n < N)
                bv = *(const float4*)(Bm + (size_t)(k0 + kk) * N + n0 + n);
            else
                bv = make_float4(0.f, 0.f, 0.f, 0.f);
            *(float4*)(&Bs[kk][n]) = bv;
        }
        __syncthreads();
#pragma unroll
        for (int k = 0; k < BK; k++) {
            float a[TM], b[TN];
#pragma unroll
            for (int i = 0; i < TM; i++) a[i] = As[k][ty * TM + i];
#pragma unroll
            for (int j = 0; j < TN; j++) b[j] = Bs[k][tx * TN + j];
#pragma unroll
            for (int i = 0; i < TM; i++)
#pragma unroll
                for (int j = 0; j < TN; j++) acc[i][j] += a[i] * b[j];
        }
        __syncthreads();
    }

#pragma unroll
    for (int i = 0; i < TM; i++) {
        int m = m0 + ty * TM + i;
#pragma unroll
        for (int j = 0; j < TN; j++) {
            int n = n0 + tx * TN + j;
            if (n < N) {
                float v = acc[i][j];
                if (BIAS) v += bias[n];
                if (RELU) v = fmaxf(v, 0.f);
                if (RES)  v += res[(size_t)m * N + n];
                Cm[(size_t)m * N + n] = v;
            }
        }
    }
}

template <bool BIAS, bool RELU, bool RES>
__global__ void sgemm_kernel(const float* __restrict__ A, const float* __restrict__ Bm,
                             const float* __restrict__ bias, const float* __restrict__ res,
                             float* __restrict__ Cm, int M, int N, int K) {
    sgemm_body<BIAS, RELU, RES>(A, Bm, bias, res, Cm, M, N, K);
}

// qkv fused via blockIdx.z
__global__ void qkv_kernel(const float* __restrict__ A,
                           const float* __restrict__ wq,
                           const float* __restrict__ wk,
                           const float* __restrict__ wv, int M) {
    const float* Bm = (blockIdx.z == 0) ? wq : (blockIdx.z == 1) ? wk : wv;
    float* O = (blockIdx.z == 0) ? g_q : (blockIdx.z == 1) ? g_k : g_v;
    sgemm_body<false, false, false>(A, Bm, nullptr, nullptr, O, M, Cc, Cc);
}

// ---------------- attention: one block per (b,h), flash-style -----------
__global__ void attn_kernel(const float* __restrict__ q, const float* __restrict__ k,
                            const float* __restrict__ v, float* __restrict__ o) {
    extern __shared__ float sm[];
    float* ks = sm;                // Tt*DHh
    float* vs = sm + Tt * DHh;     // Tt*DHh
    int b = blockIdx.y, h = blockIdx.x;
    size_t base = (size_t)b * Tt * Cc + (size_t)h * DHh;

    for (int i = threadIdx.x; i < Tt * (DHh / 4); i += blockDim.x) {
        int s = i / (DHh / 4);
        int d4 = (i % (DHh / 4)) * 4;
        *(float4*)(ks + s * DHh + d4) = *(const float4*)(k + base + (size_t)s * Cc + d4);
        *(float4*)(vs + s * DHh + d4) = *(const float4*)(v + base + (size_t)s * Cc + d4);
    }
    __syncthreads();

    int t = threadIdx.x;  // query row, 0..127
    float qr[DHh];
#pragma unroll
    for (int d4 = 0; d4 < DHh; d4 += 4) {
        float4 f = *(const float4*)(q + base + (size_t)t * Cc + d4);
        qr[d4] = f.x; qr[d4 + 1] = f.y; qr[d4 + 2] = f.z; qr[d4 + 3] = f.w;
    }
    const float scale = 0.125f;  // 1/sqrt(64)

    // pass 1: online max + sumexp over s<=t (causal)
    float m = -1e30f, lsum = 0.f;
    for (int s = 0; s <= t; s++) {
        float dot = 0.f;
#pragma unroll
        for (int d = 0; d < DHh; d++) dot += qr[d] * ks[s * DHh + d];
        dot *= scale;
        if (dot > m) { lsum = lsum * __expf(m - dot) + 1.f; m = dot; }
        else         { lsum += __expf(dot - m); }
    }
    float inv = 1.f / lsum;

    // pass 2: weighted sum of V
    float acc[DHh];
#pragma unroll
    for (int d = 0; d < DHh; d++) acc[d] = 0.f;
    for (int s = 0; s <= t; s++) {
        float dot = 0.f;
#pragma unroll
        for (int d = 0; d < DHh; d++) dot += qr[d] * ks[s * DHh + d];
        float w = __expf(dot * scale - m) * inv;
#pragma unroll
        for (int d = 0; d < DHh; d++) acc[d] += w * vs[s * DHh + d];
    }
#pragma unroll
    for (int d = 0; d < DHh; d++) o[base + (size_t)t * Cc + d] = acc[d];
}

// ---------------- NLL per row + final mean ----------------
__global__ void nll_kernel(const float* __restrict__ logits, const int* __restrict__ tgt) {
    int row = blockIdx.x;
    const float* p = logits + (size_t)row * Vv;
    float m = -1e30f;
    for (int j = threadIdx.x; j < Vv; j += blockDim.x) m = fmaxf(m, p[j]);
    m = blk_max<8>(m);
    float s = 0.f;
    for (int j = threadIdx.x; j < Vv; j += blockDim.x) s += __expf(p[j] - m);
    s = blk_sum<8>(s);
    if (threadIdx.x == 0) g_nll[row] = -(p[tgt[row]] - m - logf(s));
}

__global__ void loss_kernel(float* __restrict__ out, int M, int write_loss) {
    float s = 0.f;
    for (int i = threadIdx.x; i < M; i += blockDim.x) s += g_nll[i];
    s = blk_sum<8>(s);
    if (threadIdx.x == 0 && write_loss) out[(size_t)M * Vv] = s / (float)M;
}

// ---------------- launch ----------------
extern "C" void kernel_launch(void* const* d_in, const int* in_sizes, int n_in,
                              void* d_out, int out_size) {
    const int*   idx  = (const int*)d_in[0];
    const int*   tgt  = (const int*)d_in[1];
    const float* tok  = (const float*)d_in[2];
    const float* pos  = (const float*)d_in[3];
    const float* wq   = (const float*)d_in[4];
    const float* wk   = (const float*)d_in[5];
    const float* wv   = (const float*)d_in[6];
    const float* wo   = (const float*)d_in[7];
    const float* bo   = (const float*)d_in[8];
    const float* ln1g = (const float*)d_in[9];
    const float* ln1b = (const float*)d_in[10];
    const float* ln2g = (const float*)d_in[11];
    const float* ln2b = (const float*)d_in[12];
    const float* w1   = (const float*)d_in[13];
    const float* b1   = (const float*)d_in[14];
    const float* w2   = (const float*)d_in[15];
    const float* b2   = (const float*)d_in[16];
    const float* lnfg = (const float*)d_in[17];
    const float* lnfb = (const float*)d_in[18];
    const float* lmw  = (const float*)d_in[19];
    const float* lmb  = (const float*)d_in[20];
    float* out = (float*)d_out;

    int M  = in_sizes[0];   // 8192 tokens
    int Bb = M / Tt;

    float *x, *h, *q, *k, *v, *att, *ff;
    cudaGetSymbolAddress((void**)&x,   g_x);
    cudaGetSymbolAddress((void**)&h,   g_h);
    cudaGetSymbolAddress((void**)&q,   g_q);
    cudaGetSymbolAddress((void**)&k,   g_k);
    cudaGetSymbolAddress((void**)&v,   g_v);
    cudaGetSymbolAddress((void**)&att, g_att);
    cudaGetSymbolAddress((void**)&ff,  g_ff);

    int attn_smem = 2 * Tt * DHh * (int)sizeof(float);  // 64 KB
    cudaFuncSetAttribute(attn_kernel, cudaFuncAttributeMaxDynamicSharedMemorySize, attn_smem);

    embed_kernel<<<M, Cc>>>(idx, tok, pos);

    dim3 blk(256);
    for (int l = 0; l < Ll; l++) {
        size_t wofs = (size_t)l * Cc * Cc;
        ln_kernel<<<M, 128>>>(x, ln1g + l * Cc, ln1b + l * Cc, h);
        qkv_kernel<<<dim3(Cc / BN, M / BM, 3), blk>>>(h, wq + wofs, wk + wofs, wv + wofs, M);
        attn_kernel<<<dim3(Hh, Bb), 128, attn_smem>>>(q, k, v, att);
        sgemm_kernel<true, false, true><<<dim3(Cc / BN, M / BM), blk>>>(
            att, wo + wofs, bo + l * Cc, x, x, M, Cc, Cc);
        ln_kernel<<<M, 128>>>(x, ln2g + l * Cc, ln2b + l * Cc, h);
        sgemm_kernel<true, true, false><<<dim3(FFf / BN, M / BM), blk>>>(
            h, w1 + (size_t)l * Cc * FFf, b1 + l * FFf, nullptr, ff, M, FFf, Cc);
        sgemm_kernel<true, false, true><<<dim3(Cc / BN, M / BM), blk>>>(
            ff, w2 + (size_t)l * FFf * Cc, b2 + l * Cc, x, x, M, Cc, FFf);
    }

    ln_kernel<<<M, 128>>>(x, lnfg, lnfb, h);
    sgemm_kernel<true, false, false><<<dim3((Vv + BN - 1) / BN, M / BM), blk>>>(
        h, lmw, lmb, nullptr, out, M, Vv, Cc);

    nll_kernel<<<M, 256>>>(out, tgt);
    int wr = ((long long)out_size > (long long)M * (long long)Vv) ? 1 : 0;
    loss_kernel<<<1, 256>>>(out, M, wr);
}

// round 4
// speedup vs baseline: 1.7776x; 1.7776x over previous
#include <cuda_runtime.h>
#include <cuda_bf16.h>

// Model dims (fixed by the problem)
#define Bsz  64
#define Tt   128
#define Cc   384
#define Hh   6
#define DHh  64
#define Ll   6
#define FFf  1536
#define Vv   25000
#define NTOK (Bsz * Tt)
#define LN_EPS 1e-5f

// ---------------- scratch (device globals: allocation-free) ----------------
__device__ float g_x[NTOK * Cc];
__device__ float g_h[NTOK * Cc];
__device__ float g_q[NTOK * Cc];
__device__ float g_k[NTOK * Cc];
__device__ float g_v[NTOK * Cc];
__device__ float g_att[NTOK * Cc];
__device__ float g_ff[NTOK * FFf];
__device__ float g_nll[NTOK];

// ---------------- block reductions (deterministic) ----------------
template <int NW>
__device__ __forceinline__ float blk_sum(float v) {
    __shared__ float sh[NW];
    int lane = threadIdx.x & 31, w = threadIdx.x >> 5;
#pragma unroll
    for (int o = 16; o > 0; o >>= 1) v += __shfl_down_sync(0xffffffffu, v, o);
    if (lane == 0) sh[w] = v;
    __syncthreads();
    if (threadIdx.x == 0) {
        float t = 0.f;
#pragma unroll
        for (int i = 0; i < NW; i++) t += sh[i];
        sh[0] = t;
    }
    __syncthreads();
    float r = sh[0];
    __syncthreads();
    return r;
}

template <int NW>
__device__ __forceinline__ float blk_max(float v) {
    __shared__ float sh[NW];
    int lane = threadIdx.x & 31, w = threadIdx.x >> 5;
#pragma unroll
    for (int o = 16; o > 0; o >>= 1) v = fmaxf(v, __shfl_down_sync(0xffffffffu, v, o));
    if (lane == 0) sh[w] = v;
    __syncthreads();
    if (threadIdx.x == 0) {
        float t = sh[0];
#pragma unroll
        for (int i = 1; i < NW; i++) t = fmaxf(t, sh[i]);
        sh[0] = t;
    }
    __syncthreads();
    float r = sh[0];
    __syncthreads();
    return r;
}

// ---------------- embedding ----------------
__global__ void embed_kernel(const int* __restrict__ idx,
                             const float* __restrict__ tok,
                             const float* __restrict__ pos) {
    int i = blockIdx.x, c = threadIdx.x;
    int t = i % Tt;
    g_x[(size_t)i * Cc + c] = tok[(size_t)idx[i] * Cc + c] + pos[(size_t)t * Cc + c];
}

// ---------------- layernorm (128 threads, 3 elems/thread) ----------------
__global__ void ln_kernel(const float* __restrict__ in, const float* __restrict__ g,
                          const float* __restrict__ b, float* __restrict__ out) {
    int row = blockIdx.x;
    const float* p = in + (size_t)row * Cc;
    int c = threadIdx.x;
    float x0 = p[c], x1 = p[c + 128], x2 = p[c + 256];
    float s = blk_sum<4>(x0 + x1 + x2);
    float mu = s * (1.f / Cc);
    float d0 = x0 - mu, d1 = x1 - mu, d2 = x2 - mu;
    float s2 = blk_sum<4>(d0 * d0 + d1 * d1 + d2 * d2);
    float w = rsqrtf(s2 * (1.f / Cc) + LN_EPS);
    float* q = out + (size_t)row * Cc;
    q[c]       = d0 * w * g[c]       + b[c];
    q[c + 128] = d1 * w * g[c + 128] + b[c + 128];
    q[c + 256] = d2 * w * g[c + 256] + b[c + 256];
}

// ============================================================================
// Tensor-core GEMM: C[M,N] = A[M,K] @ B[K,N] with bf16x2 split (3 HMMA passes)
// Block 128x128, BK=32, 256 threads (8 warps as 2(m) x 4(n), warp tile 64x32)
// ============================================================================
#define GBM 128
#define GBN 128
#define GBK 32
#define LDA_S 40   // halves per As row (32 + 8 pad -> conflict-free frag reads)
#define LDB_S 40

__device__ __forceinline__ void mma16816(float* c, const unsigned* a, const unsigned* b) {
    asm volatile(
        "mma.sync.aligned.m16n8k16.row.col.f32.bf16.bf16.f32 "
        "{%0,%1,%2,%3}, {%4,%5,%6,%7}, {%8,%9}, {%0,%1,%2,%3};"
        : "+f"(c[0]), "+f"(c[1]), "+f"(c[2]), "+f"(c[3])
        : "r"(a[0]), "r"(a[1]), "r"(a[2]), "r"(a[3]), "r"(b[0]), "r"(b[1]));
}

__device__ __forceinline__ void cvt_hl(float x, __nv_bfloat16& h, __nv_bfloat16& l) {
    h = __float2bfloat16_rn(x);
    l = __float2bfloat16_rn(x - __bfloat162float(h));
}

template <bool BIAS, bool RELU, bool RES>
__device__ __forceinline__ void mgemm_body(const float* __restrict__ A,
                                           const float* __restrict__ Bm,
                                           const float* __restrict__ bias,
                                           const float* __restrict__ res,
                                           float* __restrict__ Cm,
                                           int M, int N, int K) {
    __shared__ __nv_bfloat16 Ah[GBM * LDA_S];
    __shared__ __nv_bfloat16 Al[GBM * LDA_S];
    __shared__ __nv_bfloat16 Bh[GBN * LDB_S];
    __shared__ __nv_bfloat16 Bl[GBN * LDB_S];

    int tid = threadIdx.x;
    int lane = tid & 31, warp = tid >> 5;
    int wm = warp & 1, wn = warp >> 1;           // 2 x 4 warp grid
    int m0 = blockIdx.y * GBM, n0 = blockIdx.x * GBN;
    int g = lane >> 2, tg = lane & 3;            // groupID, threadID_in_group

    float acc[4][4][4];
#pragma unroll
    for (int i = 0; i < 4; i++)
#pragma unroll
        for (int j = 0; j < 4; j++)
#pragma unroll
            for (int r = 0; r < 4; r++) acc[i][j][r] = 0.f;

    for (int k0 = 0; k0 < K; k0 += GBK) {
        // ---- stage A (128x32 fp32 -> hi/lo bf16) ----
#pragma unroll
        for (int i = 0; i < 4; i++) {
            int f = i * 256 + tid;
            int m = f >> 3, k = (f & 7) * 4;
            float4 a = *(const float4*)(A + (size_t)(m0 + m) * K + k0 + k);
            __nv_bfloat16 h0, h1, h2, h3, l0, l1, l2, l3;
            cvt_hl(a.x, h0, l0); cvt_hl(a.y, h1, l1);
            cvt_hl(a.z, h2, l2); cvt_hl(a.w, h3, l3);
            int o = m * LDA_S + k;
            *(__nv_bfloat162*)&Ah[o]     = __nv_bfloat162(h0, h1);
            *(__nv_bfloat162*)&Ah[o + 2] = __nv_bfloat162(h2, h3);
            *(__nv_bfloat162*)&Al[o]     = __nv_bfloat162(l0, l1);
            *(__nv_bfloat162*)&Al[o + 2] = __nv_bfloat162(l2, l3);
        }
        // ---- stage B transposed (32x128 fp32 -> Bs[n][k] hi/lo bf16) ----
#pragma unroll
        for (int i = 0; i < 4; i++) {
            int f = i * 256 + tid;
            int n = f & 127, k = (f >> 7) * 4;
            float b0 = 0.f, b1 = 0.f, b2 = 0.f, b3 = 0.f;
            if (n0 + n < N) {
                const float* bp = Bm + (size_t)(k0 + k) * N + n0 + n;
                b0 = bp[0]; b1 = bp[(size_t)N]; b2 = bp[2 * (size_t)N]; b3 = bp[3 * (size_t)N];
            }
            __nv_bfloat16 h0, h1, h2, h3, l0, l1, l2, l3;
            cvt_hl(b0, h0, l0); cvt_hl(b1, h1, l1);
            cvt_hl(b2, h2, l2); cvt_hl(b3, h3, l3);
            int o = n * LDB_S + k;
            *(__nv_bfloat162*)&Bh[o]     = __nv_bfloat162(h0, h1);
            *(__nv_bfloat162*)&Bh[o + 2] = __nv_bfloat162(h2, h3);
            *(__nv_bfloat162*)&Bl[o]     = __nv_bfloat162(l0, l1);
            *(__nv_bfloat162*)&Bl[o + 2] = __nv_bfloat162(l2, l3);
        }
        __syncthreads();

#pragma unroll
        for (int kc = 0; kc < GBK; kc += 16) {
            unsigned ah[4][4], al[4][4], bh[4][2], bl[4][2];
#pragma unroll
            for (int mt = 0; mt < 4; mt++) {
                int r = wm * 64 + mt * 16 + g;
                int base = r * LDA_S + kc + tg * 2;
                ah[mt][0] = *(const unsigned*)&Ah[base];
                ah[mt][1] = *(const unsigned*)&Ah[base + 8 * LDA_S];
                ah[mt][2] = *(const unsigned*)&Ah[base + 8];
                ah[mt][3] = *(const unsigned*)&Ah[base + 8 * LDA_S + 8];
                al[mt][0] = *(const unsigned*)&Al[base];
                al[mt][1] = *(const unsigned*)&Al[base + 8 * LDA_S];
                al[mt][2] = *(const unsigned*)&Al[base + 8];
                al[mt][3] = *(const unsigned*)&Al[base + 8 * LDA_S + 8];
            }
#pragma unroll
            for (int nt = 0; nt < 4; nt++) {
                int n = wn * 32 + nt * 8 + g;
                int base = n * LDB_S + kc + tg * 2;
                bh[nt][0] = *(const unsigned*)&Bh[base];
                bh[nt][1] = *(const unsigned*)&Bh[base + 8];
                bl[nt][0] = *(const unsigned*)&Bl[base];
                bl[nt][1] = *(const unsigned*)&Bl[base + 8];
            }
#pragma unroll
            for (int mt = 0; mt < 4; mt++)
#pragma unroll
                for (int nt = 0; nt < 4; nt++) mma16816(acc[mt][nt], ah[mt], bh[nt]);
#pragma unroll
            for (int mt = 0; mt < 4; mt++)
#pragma unroll
                for (int nt = 0; nt < 4; nt++) mma16816(acc[mt][nt], ah[mt], bl[nt]);
#pragma unroll
            for (int mt = 0; mt < 4; mt++)
#pragma unroll
                for (int nt = 0; nt < 4; nt++) mma16816(acc[mt][nt], al[mt], bh[nt]);
        }
        __syncthreads();
    }

    // ---- epilogue ----
#pragma unroll
    for (int mt = 0; mt < 4; mt++) {
        int r = m0 + wm * 64 + mt * 16 + g;
#pragma unroll
        for (int nt = 0; nt < 4; nt++) {
            int c = n0 + wn * 32 + nt * 8 + tg * 2;
            if (c < N) {
                float v0 = acc[mt][nt][0], v1 = acc[mt][nt][1];
                float v2 = acc[mt][nt][2], v3 = acc[mt][nt][3];
                if (BIAS) { float bb0 = bias[c], bb1 = bias[c + 1]; v0 += bb0; v1 += bb1; v2 += bb0; v3 += bb1; }
                if (RELU) { v0 = fmaxf(v0, 0.f); v1 = fmaxf(v1, 0.f); v2 = fmaxf(v2, 0.f); v3 = fmaxf(v3, 0.f); }
                size_t o0 = (size_t)r * N + c, o1 = (size_t)(r + 8) * N + c;
                if (RES) {
                    float2 r0 = *(const float2*)(res + o0), r1 = *(const float2*)(res + o1);
                    v0 += r0.x; v1 += r0.y; v2 += r1.x; v3 += r1.y;
                }
                *(float2*)(Cm + o0) = make_float2(v0, v1);
                *(float2*)(Cm + o1) = make_float2(v2, v3);
            }
        }
    }
}

template <bool BIAS, bool RELU, bool RES>
__global__ void __launch_bounds__(256)
mgemm_kernel(const float* __restrict__ A, const float* __restrict__ Bm,
             const float* __restrict__ bias, const float* __restrict__ res,
             float* __restrict__ Cm, int M, int N, int K) {
    mgemm_body<BIAS, RELU, RES>(A, Bm, bias, res, Cm, M, N, K);
}

// qkv fused via blockIdx.z
__global__ void __launch_bounds__(256)
qkv_kernel(const float* __restrict__ A, const float* __restrict__ wq,
           const float* __restrict__ wk, const float* __restrict__ wv, int M) {
    const float* Bm = (blockIdx.z == 0) ? wq : (blockIdx.z == 1) ? wk : wv;
    float* O = (blockIdx.z == 0) ? g_q : (blockIdx.z == 1) ? g_k : g_v;
    mgemm_body<false, false, false>(A, Bm, nullptr, nullptr, O, M, Cc, Cc);
}

// ---------------- attention: one block per (b,h), single-pass flash --------
// All lanes walk the same s (smem broadcast); causal mask by predicate.
__global__ void attn_kernel(const float* __restrict__ q, const float* __restrict__ k,
                            const float* __restrict__ v, float* __restrict__ o) {
    extern __shared__ float sm[];
    float* ks = sm;                // Tt*DHh
    float* vs = sm + Tt * DHh;     // Tt*DHh
    int b = blockIdx.y, h = blockIdx.x;
    size_t base = (size_t)b * Tt * Cc + (size_t)h * DHh;

    for (int i = threadIdx.x; i < Tt * (DHh / 4); i += blockDim.x) {
        int s = i / (DHh / 4);
        int d4 = (i % (DHh / 4)) * 4;
        *(float4*)(ks + s * DHh + d4) = *(const float4*)(k + base + (size_t)s * Cc + d4);
        *(float4*)(vs + s * DHh + d4) = *(const float4*)(v + base + (size_t)s * Cc + d4);
    }
    __syncthreads();

    int t = threadIdx.x;           // query row, 0..127
    int smax = t | 31;             // warp-uniform loop bound
    float qr[DHh];
#pragma unroll
    for (int d4 = 0; d4 < DHh; d4 += 4) {
        float4 f = *(const float4*)(q + base + (size_t)t * Cc + d4);
        qr[d4] = f.x; qr[d4 + 1] = f.y; qr[d4 + 2] = f.z; qr[d4 + 3] = f.w;
    }
    const float scale = 0.125f;    // 1/sqrt(64)

    float m = -1e30f, lsum = 0.f;
    float acc[DHh];
#pragma unroll
    for (int d = 0; d < DHh; d++) acc[d] = 0.f;

    for (int s = 0; s <= smax; s++) {
        // broadcast loads: same address across all lanes of the warp
        float kv[DHh], vv[DHh];
#pragma unroll
        for (int d4 = 0; d4 < DHh; d4 += 4) {
            float4 kf = *(const float4*)(ks + s * DHh + d4);
            kv[d4] = kf.x; kv[d4 + 1] = kf.y; kv[d4 + 2] = kf.z; kv[d4 + 3] = kf.w;
            float4 vf = *(const float4*)(vs + s * DHh + d4);
            vv[d4] = vf.x; vv[d4 + 1] = vf.y; vv[d4 + 2] = vf.z; vv[d4 + 3] = vf.w;
        }
        float dot = 0.f;
#pragma unroll
        for (int d = 0; d < DHh; d++) dot += qr[d] * kv[d];
        if (s <= t) {
            float p = dot * scale;
            float w;
            if (p > m) {
                float f = __expf(m - p);
                lsum = lsum * f + 1.f;
#pragma unroll
                for (int d = 0; d < DHh; d++) acc[d] *= f;
                m = p; w = 1.f;
            } else {
                w = __expf(p - m);
                lsum += w;
            }
#pragma unroll
            for (int d = 0; d < DHh; d++) acc[d] += w * vv[d];
        }
    }
    float inv = 1.f / lsum;
#pragma unroll
    for (int d = 0; d < DHh; d++) o[base + (size_t)t * Cc + d] = acc[d] * inv;
}

// ---------------- NLL per row + final mean ----------------
__global__ void nll_kernel(const float* __restrict__ logits, const int* __restrict__ tgt) {
    int row = blockIdx.x;
    const float* p = logits + (size_t)row * Vv;
    float m = -1e30f;
    for (int j = threadIdx.x; j < Vv; j += blockDim.x) m = fmaxf(m, p[j]);
    m = blk_max<8>(m);
    float s = 0.f;
    for (int j = threadIdx.x; j < Vv; j += blockDim.x) s += __expf(p[j] - m);
    s = blk_sum<8>(s);
    if (threadIdx.x == 0) g_nll[row] = -(p[tgt[row]] - m - logf(s));
}

__global__ void loss_kernel(float* __restrict__ out, int M, int write_loss) {
    float s = 0.f;
    for (int i = threadIdx.x; i < M; i += blockDim.x) s += g_nll[i];
    s = blk_sum<8>(s);
    if (threadIdx.x == 0 && write_loss) out[(size_t)M * Vv] = s / (float)M;
}

// ---------------- launch ----------------
extern "C" void kernel_launch(void* const* d_in, const int* in_sizes, int n_in,
                              void* d_out, int out_size) {
    const int*   idx  = (const int*)d_in[0];
    const int*   tgt  = (const int*)d_in[1];
    const float* tok  = (const float*)d_in[2];
    const float* pos  = (const float*)d_in[3];
    const float* wq   = (const float*)d_in[4];
    const float* wk   = (const float*)d_in[5];
    const float* wv   = (const float*)d_in[6];
    const float* wo   = (const float*)d_in[7];
    const float* bo   = (const float*)d_in[8];
    const float* ln1g = (const float*)d_in[9];
    const float* ln1b = (const float*)d_in[10];
    const float* ln2g = (const float*)d_in[11];
    const float* ln2b = (const float*)d_in[12];
    const float* w1   = (const float*)d_in[13];
    const float* b1   = (const float*)d_in[14];
    const float* w2   = (const float*)d_in[15];
    const float* b2   = (const float*)d_in[16];
    const float* lnfg = (const float*)d_in[17];
    const float* lnfb = (const float*)d_in[18];
    const float* lmw  = (const float*)d_in[19];
    const float* lmb  = (const float*)d_in[20];
    float* out = (float*)d_out;

    int M  = in_sizes[0];   // 8192 tokens
    int Bb = M / Tt;

    float *x, *h, *q, *k, *v, *att, *ff;
    cudaGetSymbolAddress((void**)&x,   g_x);
    cudaGetSymbolAddress((void**)&h,   g_h);
    cudaGetSymbolAddress((void**)&q,   g_q);
    cudaGetSymbolAddress((void**)&k,   g_k);
    cudaGetSymbolAddress((void**)&v,   g_v);
    cudaGetSymbolAddress((void**)&att, g_att);
    cudaGetSymbolAddress((void**)&ff,  g_ff);

    int attn_smem = 2 * Tt * DHh * (int)sizeof(float);  // 64 KB
    cudaFuncSetAttribute(attn_kernel, cudaFuncAttributeMaxDynamicSharedMemorySize, attn_smem);

    embed_kernel<<<M, Cc>>>(idx, tok, pos);

    dim3 blk(256);
    for (int l = 0; l < Ll; l++) {
        size_t wofs = (size_t)l * Cc * Cc;
        ln_kernel<<<M, 128>>>(x, ln1g + l * Cc, ln1b + l * Cc, h);
        qkv_kernel<<<dim3(Cc / GBN, M / GBM, 3), blk>>>(h, wq + wofs, wk + wofs, wv + wofs, M);
        attn_kernel<<<dim3(Hh, Bb), 128, attn_smem>>>(q, k, v, att);
        mgemm_kernel<true, false, true><<<dim3(Cc / GBN, M / GBM), blk>>>(
            att, wo + wofs, bo + l * Cc, x, x, M, Cc, Cc);
        ln_kernel<<<M, 128>>>(x, ln2g + l * Cc, ln2b + l * Cc, h);
        mgemm_kernel<true, true, false><<<dim3(FFf / GBN, M / GBM), blk>>>(
            h, w1 + (size_t)l * Cc * FFf, b1 + l * FFf, nullptr, ff, M, FFf, Cc);
        mgemm_kernel<true, false, true><<<dim3(Cc / GBN, M / GBM), blk>>>(
            ff, w2 + (size_t)l * FFf * Cc, b2 + l * Cc, x, x, M, Cc, FFf);
    }

    ln_kernel<<<M, 128>>>(x, lnfg, lnfb, h);
    mgemm_kernel<true, false, false><<<dim3((Vv + GBN - 1) / GBN, M / GBM), blk>>>(
        h, lmw, lmb, nullptr, out, M, Vv, Cc);

    nll_kernel<<<M, 256>>>(out, tgt);
    int wr = ((long long)out_size > (long long)M * (long long)Vv) ? 1 : 0;
    loss_kernel<<<1, 256>>>(out, M, wr);
}

// round 5
// speedup vs baseline: 2.0878x; 1.1745x over previous
#include <cuda_runtime.h>
#include <cuda_bf16.h>

#define Bsz  64
#define Tt   128
#define Cc   384
#define Hh   6
#define DHh  64
#define Ll   6
#define FFf  1536
#define Vv   25000
#define NTOK (Bsz * Tt)
#define LN_EPS 1e-5f

typedef __nv_bfloat16 bf16;
typedef __nv_bfloat162 bf162;

// ---------------- scratch (device globals: allocation-free) ----------------
__device__ float g_x[NTOK * Cc];
__device__ float g_q[NTOK * Cc];
__device__ float g_k[NTOK * Cc];
__device__ float g_v[NTOK * Cc];
__device__ float g_nll[NTOK];

// split-bf16 activations
__device__ bf16 g_hh[NTOK * Cc],  g_hl[NTOK * Cc];
__device__ bf16 g_ath[NTOK * Cc], g_atl[NTOK * Cc];
__device__ bf16 g_ffh[NTOK * FFf], g_ffl[NTOK * FFf];

// transposed split-bf16 weights [N][K]
__device__ bf16 g_wqh[Ll * Cc * Cc],  g_wql[Ll * Cc * Cc];
__device__ bf16 g_wkh[Ll * Cc * Cc],  g_wkl[Ll * Cc * Cc];
__device__ bf16 g_wvh[Ll * Cc * Cc],  g_wvl[Ll * Cc * Cc];
__device__ bf16 g_woh[Ll * Cc * Cc],  g_wol[Ll * Cc * Cc];
__device__ bf16 g_w1h[Ll * Cc * FFf], g_w1l[Ll * Cc * FFf];
__device__ bf16 g_w2h[Ll * FFf * Cc], g_w2l[Ll * FFf * Cc];
__device__ bf16 g_lmh[(size_t)Vv * Cc], g_lml[(size_t)Vv * Cc];

__device__ __forceinline__ void cvt_hl(float x, bf16& h, bf16& l) {
    h = __float2bfloat16_rn(x);
    l = __float2bfloat16_rn(x - __bfloat162float(h));
}

// ---------------- weight transpose + split: w[K][N] -> th/tl[N][K] ---------
__global__ void wsplit_t(const float* __restrict__ w, bf16* __restrict__ th,
                         bf16* __restrict__ tl, int K, int N) {
    __shared__ float tile[32][33];
    int l = blockIdx.z;
    const float* wp = w + (size_t)l * K * N;
    bf16* thp = th + (size_t)l * K * N;
    bf16* tlp = tl + (size_t)l * K * N;
    int n0 = blockIdx.x * 32, k0 = blockIdx.y * 32;
    int tx = threadIdx.x, ty = threadIdx.y;  // 32 x 8
#pragma unroll
    for (int i = 0; i < 4; i++) {
        int k = k0 + ty + 8 * i, n = n0 + tx;
        tile[ty + 8 * i][tx] = (k < K && n < N) ? wp[(size_t)k * N + n] : 0.f;
    }
    __syncthreads();
#pragma unroll
    for (int i = 0; i < 4; i++) {
        int n = n0 + ty + 8 * i, k = k0 + tx;
        if (n < N && k < K) {
            bf16 h, lo;
            cvt_hl(tile[tx][ty + 8 * i], h, lo);
            thp[(size_t)n * K + k] = h;
            tlp[(size_t)n * K + k] = lo;
        }
    }
}

// ---------------- embedding ----------------
__global__ void embed_kernel(const int* __restrict__ idx,
                             const float* __restrict__ tok,
                             const float* __restrict__ pos) {
    int i = blockIdx.x, c = threadIdx.x;
    int t = i % Tt;
    g_x[(size_t)i * Cc + c] = tok[(size_t)idx[i] * Cc + c] + pos[(size_t)t * Cc + c];
}

// ---------------- layernorm -> split bf16 ----------------
template <int NW>
__device__ __forceinline__ float blk_sum(float v) {
    __shared__ float sh[NW];
    int lane = threadIdx.x & 31, w = threadIdx.x >> 5;
#pragma unroll
    for (int o = 16; o > 0; o >>= 1) v += __shfl_down_sync(0xffffffffu, v, o);
    if (lane == 0) sh[w] = v;
    __syncthreads();
    if (threadIdx.x == 0) {
        float t = 0.f;
#pragma unroll
        for (int i = 0; i < NW; i++) t += sh[i];
        sh[0] = t;
    }
    __syncthreads();
    float r = sh[0];
    __syncthreads();
    return r;
}

__global__ void ln_split_kernel(const float* __restrict__ in, const float* __restrict__ g,
                                const float* __restrict__ b, bf16* __restrict__ oh,
                                bf16* __restrict__ ol) {
    int row = blockIdx.x;
    const float* p = in + (size_t)row * Cc;
    int c = threadIdx.x;
    float x0 = p[c], x1 = p[c + 128], x2 = p[c + 256];
    float s = blk_sum<4>(x0 + x1 + x2);
    float mu = s * (1.f / Cc);
    float d0 = x0 - mu, d1 = x1 - mu, d2 = x2 - mu;
    float s2 = blk_sum<4>(d0 * d0 + d1 * d1 + d2 * d2);
    float w = rsqrtf(s2 * (1.f / Cc) + LN_EPS);
    size_t ro = (size_t)row * Cc;
#pragma unroll
    for (int i = 0; i < 3; i++) {
        int cc = c + i * 128;
        float v = ((i == 0 ? d0 : i == 1 ? d1 : d2)) * w * g[cc] + b[cc];
        bf16 h, lo;
        cvt_hl(v, h, lo);
        oh[ro + cc] = h;
        ol[ro + cc] = lo;
    }
}

// ============================================================================
// bf16 split GEMM with cp.async double buffering
// C[M,N] = A[M,K] @ B^T  where A = Ah+Al [M][K], B^T = Bh+Bl [N][K]
// Block 128x128, BK=32, 256 threads, warp tile 64x32
// ============================================================================
#define GBM 128
#define GBN 128
#define GBK 32
#define LDS_K 40
#define STAGE_H (4 * GBM * LDS_K)       // halves per stage (20480)
#define STAGE_B (STAGE_H * 2)           // bytes per stage
#define GEMM_SMEM (2 * STAGE_B)         // 81920

__device__ __forceinline__ void mma16816(float* c, const unsigned* a, const unsigned* b) {
    asm volatile(
        "mma.sync.aligned.m16n8k16.row.col.f32.bf16.bf16.f32 "
        "{%0,%1,%2,%3}, {%4,%5,%6,%7}, {%8,%9}, {%0,%1,%2,%3};"
        : "+f"(c[0]), "+f"(c[1]), "+f"(c[2]), "+f"(c[3])
        : "r"(a[0]), "r"(a[1]), "r"(a[2]), "r"(a[3]), "r"(b[0]), "r"(b[1]));
}

__device__ __forceinline__ void cpa16(unsigned dst, const void* src, int szn) {
    asm volatile("cp.async.cg.shared.global [%0], [%1], 16, %2;"
                 :: "r"(dst), "l"(src), "r"(szn));
}

template <bool BIAS, bool RELU, bool RES, bool SPLIT>
__device__ __forceinline__ void bgemm_body(
    const bf16* __restrict__ Ah_g, const bf16* __restrict__ Al_g,
    const bf16* __restrict__ Bh_g, const bf16* __restrict__ Bl_g,
    const float* __restrict__ bias, const float* __restrict__ res,
    float* __restrict__ Cf, bf16* __restrict__ Oh, bf16* __restrict__ Ol,
    int M, int N, int K) {
    extern __shared__ bf16 sm[];
    unsigned sbase = (unsigned)__cvta_generic_to_shared(sm);

    int tid = threadIdx.x;
    int lane = tid & 31, warp = tid >> 5;
    int wm = warp & 1, wn = warp >> 1;
    int m0 = blockIdx.y * GBM, n0 = blockIdx.x * GBN;
    int g = lane >> 2, tg = lane & 3;

    float acc[4][4][4];
#pragma unroll
    for (int i = 0; i < 4; i++)
#pragma unroll
        for (int j = 0; j < 4; j++)
#pragma unroll
            for (int r = 0; r < 4; r++) acc[i][j][r] = 0.f;

    const int NT = K / GBK;

    auto load_tile = [&](int kt, int st) {
        int k0 = kt * GBK;
        unsigned sb = sbase + st * STAGE_B;
#pragma unroll
        for (int r = 0; r < 2; r++) {
            int cid = tid + r * 256;
            int row = cid >> 2, kch = (cid & 3) * 8;
            unsigned d = sb + (unsigned)(row * LDS_K + kch) * 2;
            size_t aoff = (size_t)(m0 + row) * K + k0 + kch;
            cpa16(d,                 Ah_g + aoff, 16);
            cpa16(d + 5120u * 2u,    Al_g + aoff, 16);
            int bn = n0 + row;
            int ok = (bn < N) ? 16 : 0;
            size_t boff = (bn < N) ? ((size_t)bn * K + k0 + kch) : 0;
            cpa16(d + 10240u * 2u,   Bh_g + boff, ok);
            cpa16(d + 15360u * 2u,   Bl_g + boff, ok);
        }
    };

    load_tile(0, 0);
    asm volatile("cp.async.commit_group;");

    for (int t = 0; t < NT; t++) {
        asm volatile("cp.async.wait_group 0;");
        __syncthreads();
        if (t + 1 < NT) {
            load_tile(t + 1, (t + 1) & 1);
            asm volatile("cp.async.commit_group;");
        }
        const bf16* Ah_s = sm + (t & 1) * STAGE_H;
        const bf16* Al_s = Ah_s + 5120;
        const bf16* Bh_s = Ah_s + 10240;
        const bf16* Bl_s = Ah_s + 15360;
#pragma unroll
        for (int kc = 0; kc < GBK; kc += 16) {
            unsigned ah[4][4], al[4][4], bh[4][2], bl[4][2];
#pragma unroll
            for (int mt = 0; mt < 4; mt++) {
                int r = wm * 64 + mt * 16 + g;
                int base = r * LDS_K + kc + tg * 2;
                ah[mt][0] = *(const unsigned*)&Ah_s[base];
                ah[mt][1] = *(const unsigned*)&Ah_s[base + 8 * LDS_K];
                ah[mt][2] = *(const unsigned*)&Ah_s[base + 8];
                ah[mt][3] = *(const unsigned*)&Ah_s[base + 8 * LDS_K + 8];
                al[mt][0] = *(const unsigned*)&Al_s[base];
                al[mt][1] = *(const unsigned*)&Al_s[base + 8 * LDS_K];
                al[mt][2] = *(const unsigned*)&Al_s[base + 8];
                al[mt][3] = *(const unsigned*)&Al_s[base + 8 * LDS_K + 8];
            }
#pragma unroll
            for (int nt = 0; nt < 4; nt++) {
                int n = wn * 32 + nt * 8 + g;
                int base = n * LDS_K + kc + tg * 2;
                bh[nt][0] = *(const unsigned*)&Bh_s[base];
                bh[nt][1] = *(const unsigned*)&Bh_s[base + 8];
                bl[nt][0] = *(const unsigned*)&Bl_s[base];
                bl[nt][1] = *(const unsigned*)&Bl_s[base + 8];
            }
#pragma unroll
            for (int mt = 0; mt < 4; mt++)
#pragma unroll
                for (int nt = 0; nt < 4; nt++) mma16816(acc[mt][nt], ah[mt], bh[nt]);
#pragma unroll
            for (int mt = 0; mt < 4; mt++)
#pragma unroll
                for (int nt = 0; nt < 4; nt++) mma16816(acc[mt][nt], ah[mt], bl[nt]);
#pragma unroll
            for (int mt = 0; mt < 4; mt++)
#pragma unroll
                for (int nt = 0; nt < 4; nt++) mma16816(acc[mt][nt], al[mt], bh[nt]);
        }
        __syncthreads();
    }

    // epilogue
#pragma unroll
    for (int mt = 0; mt < 4; mt++) {
        int r = m0 + wm * 64 + mt * 16 + g;
#pragma unroll
        for (int nt = 0; nt < 4; nt++) {
            int c = n0 + wn * 32 + nt * 8 + tg * 2;
            if (c < N) {
                float v0 = acc[mt][nt][0], v1 = acc[mt][nt][1];
                float v2 = acc[mt][nt][2], v3 = acc[mt][nt][3];
                if (BIAS) { float b0 = bias[c], b1 = bias[c + 1]; v0 += b0; v1 += b1; v2 += b0; v3 += b1; }
                if (RELU) { v0 = fmaxf(v0, 0.f); v1 = fmaxf(v1, 0.f); v2 = fmaxf(v2, 0.f); v3 = fmaxf(v3, 0.f); }
                size_t o0 = (size_t)r * N + c, o1 = (size_t)(r + 8) * N + c;
                if (SPLIT) {
                    bf16 h0, l0, h1, l1, h2, l2, h3, l3;
                    cvt_hl(v0, h0, l0); cvt_hl(v1, h1, l1);
                    cvt_hl(v2, h2, l2); cvt_hl(v3, h3, l3);
                    *(bf162*)(Oh + o0) = bf162(h0, h1);
                    *(bf162*)(Oh + o1) = bf162(h2, h3);
                    *(bf162*)(Ol + o0) = bf162(l0, l1);
                    *(bf162*)(Ol + o1) = bf162(l2, l3);
                } else {
                    if (RES) {
                        float2 r0 = *(const float2*)(res + o0), r1 = *(const float2*)(res + o1);
                        v0 += r0.x; v1 += r0.y; v2 += r1.x; v3 += r1.y;
                    }
                    *(float2*)(Cf + o0) = make_float2(v0, v1);
                    *(float2*)(Cf + o1) = make_float2(v2, v3);
                }
            }
        }
    }
}

template <bool BIAS, bool RELU, bool RES, bool SPLIT>
__global__ void __launch_bounds__(256)
bgemm_kernel(const bf16* Ah, const bf16* Al, const bf16* Bh, const bf16* Bl,
             const float* bias, const float* res, float* Cf, bf16* Oh, bf16* Ol,
             int M, int N, int K) {
    bgemm_body<BIAS, RELU, RES, SPLIT>(Ah, Al, Bh, Bl, bias, res, Cf, Oh, Ol, M, N, K);
}

// fused qkv via blockIdx.z
__global__ void __launch_bounds__(256)
qkv_kernel(const bf16* Ah, const bf16* Al,
           const bf16* qh, const bf16* ql, const bf16* kh, const bf16* kl,
           const bf16* vh, const bf16* vl,
           float* oq, float* ok, float* ov, int M) {
    const bf16* Bh = (blockIdx.z == 0) ? qh : (blockIdx.z == 1) ? kh : vh;
    const bf16* Bl = (blockIdx.z == 0) ? ql : (blockIdx.z == 1) ? kl : vl;
    float* O = (blockIdx.z == 0) ? oq : (blockIdx.z == 1) ? ok : ov;
    bgemm_body<false, false, false, false>(Ah, Al, Bh, Bl, nullptr, nullptr, O,
                                           nullptr, nullptr, M, Cc, Cc);
}

// ---------------- attention: warp per query, lanes split DH ----------------
__global__ void attn_kernel(const float* __restrict__ q, const float* __restrict__ k,
                            const float* __restrict__ v, bf16* __restrict__ oh,
                            bf16* __restrict__ ol) {
    extern __shared__ float2 sm2[];
    float2* ks2 = sm2;              // [Tt][32]
    float2* vs2 = sm2 + Tt * 32;
    int b = blockIdx.y, h = blockIdx.x;
    size_t base = (size_t)b * Tt * Cc + (size_t)h * DHh;

    for (int j = threadIdx.x; j < Tt * 32; j += blockDim.x) {
        int s = j >> 5, pair = j & 31;
        ks2[j] = *(const float2*)(k + base + (size_t)s * Cc + pair * 2);
        vs2[j] = *(const float2*)(v + base + (size_t)s * Cc + pair * 2);
    }
    __syncthreads();

    int lane = threadIdx.x & 31, warp = threadIdx.x >> 5;  // 8 warps
    const float scale = 0.125f;

    for (int j = 0; j < 16; j++) {
        int t = warp + 8 * j;  // interleaved for balance
        float2 qv = *(const float2*)(q + base + (size_t)t * Cc + lane * 2);
        float m = -1e30f, ls = 0.f;
        float ax = 0.f, ay = 0.f;
        for (int s = 0; s <= t; s++) {
            float2 kf = ks2[s * 32 + lane];
            float d = qv.x * kf.x + qv.y * kf.y;
#pragma unroll
            for (int o = 16; o > 0; o >>= 1) d += __shfl_xor_sync(0xffffffffu, d, o);
            d *= scale;
            float2 vf = vs2[s * 32 + lane];
            if (d > m) {
                float f = __expf(m - d);
                ls = ls * f + 1.f;
                ax = ax * f + vf.x;
                ay = ay * f + vf.y;
                m = d;
            } else {
                float w = __expf(d - m);
                ls += w;
                ax += w * vf.x;
                ay += w * vf.y;
            }
        }
        float inv = 1.f / ls;
        bf16 hx, lx, hy, ly;
        cvt_hl(ax * inv, hx, lx);
        cvt_hl(ay * inv, hy, ly);
        size_t oo = base + (size_t)t * Cc + lane * 2;
        *(bf162*)(oh + oo) = bf162(hx, hy);
        *(bf162*)(ol + oo) = bf162(lx, ly);
    }
}

// ---------------- single-pass NLL ----------------
__global__ void nll_kernel(const float* __restrict__ logits, const int* __restrict__ tgt) {
    int row = blockIdx.x;
    const float* p = logits + (size_t)row * Vv;
    float m = -1e30f, s = 0.f;
    for (int j = threadIdx.x; j < Vv; j += 256) {
        float x = p[j];
        if (x > m) { s = s * __expf(m - x) + 1.f; m = x; }
        else       { s += __expf(x - m); }
    }
    int lane = threadIdx.x & 31, w = threadIdx.x >> 5;
#pragma unroll
    for (int o = 16; o > 0; o >>= 1) {
        float om = __shfl_xor_sync(0xffffffffu, m, o);
        float os = __shfl_xor_sync(0xffffffffu, s, o);
        float nm = fmaxf(m, om);
        s = s * __expf(m - nm) + os * __expf(om - nm);
        m = nm;
    }
    __shared__ float shm[8], shs[8];
    if (lane == 0) { shm[w] = m; shs[w] = s; }
    __syncthreads();
    if (threadIdx.x == 0) {
        float M0 = shm[0], S0 = shs[0];
#pragma unroll
        for (int i = 1; i < 8; i++) {
            float nm = fmaxf(M0, shm[i]);
            S0 = S0 * __expf(M0 - nm) + shs[i] * __expf(shm[i] - nm);
            M0 = nm;
        }
        g_nll[row] = -(p[tgt[row]] - M0 - logf(S0));
    }
}

__global__ void loss_kernel(float* __restrict__ out, int M, int write_loss) {
    float s = 0.f;
    for (int i = threadIdx.x; i < M; i += 256) s += g_nll[i];
    int lane = threadIdx.x & 31, w = threadIdx.x >> 5;
#pragma unroll
    for (int o = 16; o > 0; o >>= 1) s += __shfl_down_sync(0xffffffffu, s, o);
    __shared__ float sh[8];
    if (lane == 0) sh[w] = s;
    __syncthreads();
    if (threadIdx.x == 0 && write_loss) {
        float t = 0.f;
#pragma unroll
        for (int i = 0; i < 8; i++) t += sh[i];
        out[(size_t)M * Vv] = t / (float)M;
    }
}

// ---------------- launch ----------------
extern "C" void kernel_launch(void* const* d_in, const int* in_sizes, int n_in,
                              void* d_out, int out_size) {
    const int*   idx  = (const int*)d_in[0];
    const int*   tgt  = (const int*)d_in[1];
    const float* tok  = (const float*)d_in[2];
    const float* pos  = (const float*)d_in[3];
    const float* wq   = (const float*)d_in[4];
    const float* wk   = (const float*)d_in[5];
    const float* wv   = (const float*)d_in[6];
    const float* wo   = (const float*)d_in[7];
    const float* bo   = (const float*)d_in[8];
    const float* ln1g = (const float*)d_in[9];
    const float* ln1b = (const float*)d_in[10];
    const float* ln2g = (const float*)d_in[11];
    const float* ln2b = (const float*)d_in[12];
    const float* w1   = (const float*)d_in[13];
    const float* b1   = (const float*)d_in[14];
    const float* w2   = (const float*)d_in[15];
    const float* b2   = (const float*)d_in[16];
    const float* lnfg = (const float*)d_in[17];
    const float* lnfb = (const float*)d_in[18];
    const float* lmw  = (const float*)d_in[19];
    const float* lmb  = (const float*)d_in[20];
    float* out = (float*)d_out;

    int M  = in_sizes[0];
    int Bb = M / Tt;

    float *x, *q, *k, *v;
    bf16 *hh, *hl, *ath, *atl, *ffh, *ffl;
    bf16 *wqh, *wql, *wkh, *wkl, *wvh, *wvl, *woh, *wol;
    bf16 *w1h, *w1l, *w2h, *w2l, *lmh, *lml;
    cudaGetSymbolAddress((void**)&x, g_x);
    cudaGetSymbolAddress((void**)&q, g_q);
    cudaGetSymbolAddress((void**)&k, g_k);
    cudaGetSymbolAddress((void**)&v, g_v);
    cudaGetSymbolAddress((void**)&hh, g_hh);   cudaGetSymbolAddress((void**)&hl, g_hl);
    cudaGetSymbolAddress((void**)&ath, g_ath); cudaGetSymbolAddress((void**)&atl, g_atl);
    cudaGetSymbolAddress((void**)&ffh, g_ffh); cudaGetSymbolAddress((void**)&ffl, g_ffl);
    cudaGetSymbolAddress((void**)&wqh, g_wqh); cudaGetSymbolAddress((void**)&wql, g_wql);
    cudaGetSymbolAddress((void**)&wkh, g_wkh); cudaGetSymbolAddress((void**)&wkl, g_wkl);
    cudaGetSymbolAddress((void**)&wvh, g_wvh); cudaGetSymbolAddress((void**)&wvl, g_wvl);
    cudaGetSymbolAddress((void**)&woh, g_woh); cudaGetSymbolAddress((void**)&wol, g_wol);
    cudaGetSymbolAddress((void**)&w1h, g_w1h); cudaGetSymbolAddress((void**)&w1l, g_w1l);
    cudaGetSymbolAddress((void**)&w2h, g_w2h); cudaGetSymbolAddress((void**)&w2l, g_w2l);
    cudaGetSymbolAddress((void**)&lmh, g_lmh); cudaGetSymbolAddress((void**)&lml, g_lml);

    int attn_smem = 2 * Tt * 32 * (int)sizeof(float2);  // 64 KB
    cudaFuncSetAttribute(attn_kernel, cudaFuncAttributeMaxDynamicSharedMemorySize, attn_smem);
    cudaFuncSetAttribute(qkv_kernel, cudaFuncAttributeMaxDynamicSharedMemorySize, GEMM_SMEM);
    cudaFuncSetAttribute(bgemm_kernel<true, false, true, false>,
                         cudaFuncAttributeMaxDynamicSharedMemorySize, GEMM_SMEM);
    cudaFuncSetAttribute(bgemm_kernel<true, true, false, true>,
                         cudaFuncAttributeMaxDynamicSharedMemorySize, GEMM_SMEM);
    cudaFuncSetAttribute(bgemm_kernel<true, false, false, false>,
                         cudaFuncAttributeMaxDynamicSharedMemorySize, GEMM_SMEM);

    // weight prep (transpose + split)
    dim3 tb(32, 8);
    wsplit_t<<<dim3(Cc / 32, Cc / 32, Ll), tb>>>(wq, wqh, wql, Cc, Cc);
    wsplit_t<<<dim3(Cc / 32, Cc / 32, Ll), tb>>>(wk, wkh, wkl, Cc, Cc);
    wsplit_t<<<dim3(Cc / 32, Cc / 32, Ll), tb>>>(wv, wvh, wvl, Cc, Cc);
    wsplit_t<<<dim3(Cc / 32, Cc / 32, Ll), tb>>>(wo, woh, wol, Cc, Cc);
    wsplit_t<<<dim3(FFf / 32, Cc / 32, Ll), tb>>>(w1, w1h, w1l, Cc, FFf);
    wsplit_t<<<dim3(Cc / 32, FFf / 32, Ll), tb>>>(w2, w2h, w2l, FFf, Cc);
    wsplit_t<<<dim3((Vv + 31) / 32, Cc / 32, 1), tb>>>(lmw, lmh, lml, Cc, Vv);

    embed_kernel<<<M, Cc>>>(idx, tok, pos);

    dim3 blk(256);
    for (int l = 0; l < Ll; l++) {
        size_t wofs = (size_t)l * Cc * Cc;
        size_t f1 = (size_t)l * Cc * FFf;
        ln_split_kernel<<<M, 128>>>(x, ln1g + l * Cc, ln1b + l * Cc, hh, hl);
        qkv_kernel<<<dim3(Cc / GBN, M / GBM, 3), blk, GEMM_SMEM>>>(
            hh, hl, wqh + wofs, wql + wofs, wkh + wofs, wkl + wofs,
            wvh + wofs, wvl + wofs, q, k, v, M);
        attn_kernel<<<dim3(Hh, Bb), 256, attn_smem>>>(q, k, v, ath, atl);
        bgemm_kernel<true, false, true, false><<<dim3(Cc / GBN, M / GBM), blk, GEMM_SMEM>>>(
            ath, atl, woh + wofs, wol + wofs, bo + l * Cc, x, x, nullptr, nullptr, M, Cc, Cc);
        ln_split_kernel<<<M, 128>>>(x, ln2g + l * Cc, ln2b + l * Cc, hh, hl);
        bgemm_kernel<true, true, false, true><<<dim3(FFf / GBN, M / GBM), blk, GEMM_SMEM>>>(
            hh, hl, w1h + f1, w1l + f1, b1 + l * FFf, nullptr, nullptr, ffh, ffl, M, FFf, Cc);
        bgemm_kernel<true, false, true, false><<<dim3(Cc / GBN, M / GBM), blk, GEMM_SMEM>>>(
            ffh, ffl, w2h + f1, w2l + f1, b2 + l * Cc, x, x, nullptr, nullptr, M, Cc, FFf);
    }

    ln_split_kernel<<<M, 128>>>(x, lnfg, lnfb, hh, hl);
    bgemm_kernel<true, false, false, false><<<dim3((Vv + GBN - 1) / GBN, M / GBM), blk, GEMM_SMEM>>>(
        hh, hl, lmh, lml, lmb, nullptr, out, nullptr, nullptr, M, Vv, Cc);

    nll_kernel<<<M, 256>>>(out, tgt);
    int wr = ((long long)out_size > (long long)M * (long long)Vv) ? 1 : 0;
    loss_kernel<<<1, 256>>>(out, M, wr);
}